// round 1
// baseline (speedup 1.0000x reference)
#include <cuda_runtime.h>
#include <cuda_bf16.h>

#define D_MODEL 1024
#define D_INNER 2048
#define D_STATE 16
#define DT_RANK 64
#define D_CONV  4
#define N_LAYER 4
#define VOCAB   32000
#define Bb      2
#define Ll      1024
#define ROWS    (Bb * Ll)   // 2048

// ---------------- scratch (static device arrays; no allocs) ----------------
__device__ float g_x [ROWS * D_MODEL];       // residual stream
__device__ float g_xn[ROWS * D_MODEL];       // normed
__device__ float g_xz[ROWS * 2 * D_INNER];   // in_proj output (u|z)
__device__ float g_u [ROWS * D_INNER];       // conv+silu output
__device__ float g_dbl[ROWS * (DT_RANK + 2 * D_STATE)]; // x_proj output (96)
__device__ float g_dt[ROWS * D_INNER];       // softplus(dt)
__device__ float g_y [ROWS * D_INNER];       // scan output (gated)

// ---------------- embedding gather ----------------
__global__ void embed_kernel(const int* __restrict__ tokens,
                             const float* __restrict__ emb) {
    int idx = blockIdx.x * blockDim.x + threadIdx.x;
    if (idx >= ROWS * D_MODEL) return;
    int row = idx / D_MODEL;
    int c   = idx % D_MODEL;
    g_x[idx] = emb[tokens[row] * D_MODEL + c];
}

// ---------------- rmsnorm: one block per row ----------------
__global__ void rmsnorm_kernel(const float* __restrict__ in,
                               const float* __restrict__ w,
                               float* __restrict__ out) {
    __shared__ float red[8];
    int row = blockIdx.x;
    const float* x = in + row * D_MODEL;
    float s = 0.f;
    // 256 threads, 4 elems each via float4
    const float4* x4 = reinterpret_cast<const float4*>(x);
    float4 v = x4[threadIdx.x];
    s = v.x * v.x + v.y * v.y + v.z * v.z + v.w * v.w;
    // warp reduce
    #pragma unroll
    for (int o = 16; o > 0; o >>= 1) s += __shfl_xor_sync(0xffffffffu, s, o);
    if ((threadIdx.x & 31) == 0) red[threadIdx.x >> 5] = s;
    __syncthreads();
    if (threadIdx.x < 8) {
        float t = red[threadIdx.x];
        #pragma unroll
        for (int o = 4; o > 0; o >>= 1) t += __shfl_xor_sync(0xffu, t, o);
        if (threadIdx.x == 0) red[0] = t;
    }
    __syncthreads();
    float rs = rsqrtf(red[0] * (1.0f / D_MODEL) + 1e-5f);
    const float4* w4 = reinterpret_cast<const float4*>(w);
    float4 wv = w4[threadIdx.x];
    float4 o4;
    o4.x = v.x * rs * wv.x; o4.y = v.y * rs * wv.y;
    o4.z = v.z * rs * wv.z; o4.w = v.w * rs * wv.w;
    reinterpret_cast<float4*>(out + row * D_MODEL)[threadIdx.x] = o4;
}

// ---------------- generic SGEMM, C = A[M,K] * B[K,N] (+epilogue) ----------------
// EPI 0: plain  EPI 1: softplus(acc + bias[col])  EPI 2: acc + res[row*ldc+col]
template <int EPI>
__global__ __launch_bounds__(256)
void sgemm_kernel(int M, int N, int K,
                  const float* __restrict__ A, int lda,
                  const float* __restrict__ B, int ldb,
                  float* __restrict__ C, int ldc,
                  const float* __restrict__ aux) {
    constexpr int BM = 128, BN = 128, BK = 8, TM = 8, TN = 8;
    __shared__ float As[BK][BM];
    __shared__ float Bs[BK][BN];
    int tid = threadIdx.x;
    int blockRow = blockIdx.y * BM;
    int blockCol = blockIdx.x * BN;
    int tr = tid / 16;     // 0..15
    int tc = tid % 16;     // 0..15

    float acc[TM][TN];
    #pragma unroll
    for (int i = 0; i < TM; i++)
        #pragma unroll
        for (int j = 0; j < TN; j++) acc[i][j] = 0.f;

    for (int k0 = 0; k0 < K; k0 += BK) {
        #pragma unroll
        for (int i = 0; i < 4; i++) {
            int idx = tid + i * 256;
            int r = idx / BK, c = idx % BK;
            int gr = blockRow + r, gc = k0 + c;
            As[c][r] = (gr < M && gc < K) ? A[gr * lda + gc] : 0.f;
        }
        #pragma unroll
        for (int i = 0; i < 4; i++) {
            int idx = tid + i * 256;
            int r = idx / BN, c = idx % BN;
            int gr = k0 + r, gc = blockCol + c;
            Bs[r][c] = (gr < K && gc < N) ? B[gr * ldb + gc] : 0.f;
        }
        __syncthreads();
        #pragma unroll
        for (int k = 0; k < BK; k++) {
            float ra[TM], rb[TN];
            float4 a0 = reinterpret_cast<float4*>(&As[k][tr * TM])[0];
            float4 a1 = reinterpret_cast<float4*>(&As[k][tr * TM])[1];
            ra[0] = a0.x; ra[1] = a0.y; ra[2] = a0.z; ra[3] = a0.w;
            ra[4] = a1.x; ra[5] = a1.y; ra[6] = a1.z; ra[7] = a1.w;
            float4 b0 = reinterpret_cast<float4*>(&Bs[k][tc * TN])[0];
            float4 b1 = reinterpret_cast<float4*>(&Bs[k][tc * TN])[1];
            rb[0] = b0.x; rb[1] = b0.y; rb[2] = b0.z; rb[3] = b0.w;
            rb[4] = b1.x; rb[5] = b1.y; rb[6] = b1.z; rb[7] = b1.w;
            #pragma unroll
            for (int i = 0; i < TM; i++)
                #pragma unroll
                for (int j = 0; j < TN; j++)
                    acc[i][j] = fmaf(ra[i], rb[j], acc[i][j]);
        }
        __syncthreads();
    }

    #pragma unroll
    for (int i = 0; i < TM; i++) {
        int gr = blockRow + tr * TM + i;
        if (gr >= M) continue;
        #pragma unroll
        for (int j = 0; j < TN; j++) {
            int gc = blockCol + tc * TN + j;
            if (gc >= N) continue;
            float v = acc[i][j];
            if (EPI == 1) {
                v += aux[gc];
                v = (v > 20.f) ? v : log1pf(__expf(v));
            } else if (EPI == 2) {
                v += aux[gr * ldc + gc];
            }
            C[gr * ldc + gc] = v;
        }
    }
}

// ---------------- depthwise causal conv1d + silu ----------------
__global__ void conv_silu_kernel(const float* __restrict__ conv_w,
                                 const float* __restrict__ conv_b) {
    int idx = blockIdx.x * blockDim.x + threadIdx.x;
    if (idx >= ROWS * D_INNER) return;
    int d = idx % D_INNER;
    int row = idx / D_INNER;       // b*L + l
    int l = row % Ll;
    int rowbase = row - l;         // b*L
    float acc = conv_b[d];
    #pragma unroll
    for (int k = 0; k < D_CONV; k++) {
        int ll = l - (D_CONV - 1) + k;
        if (ll >= 0)
            acc = fmaf(conv_w[d * D_CONV + k],
                       g_xz[(size_t)(rowbase + ll) * (2 * D_INNER) + d], acc);
    }
    g_u[idx] = acc / (1.f + __expf(-acc));   // silu
}

// ---------------- selective scan ----------------
// one 16-lane segment per (b,d) channel; lane = state index n
__global__ void scan_kernel(const float* __restrict__ A_log,
                            const float* __restrict__ Dp) {
    int warp = (blockIdx.x * blockDim.x + threadIdx.x) >> 5;
    int lane = threadIdx.x & 31;
    int n = lane & 15;
    int ch = warp * 2 + (lane >> 4);          // 0..4095
    if (ch >= Bb * D_INNER) return;
    int b = ch / D_INNER;
    int d = ch % D_INNER;

    float An = -__expf(A_log[d * D_STATE + n]);
    float Dd = Dp[d];
    float h = 0.f;

    int base = b * Ll;
    for (int l = 0; l < Ll; l++) {
        int r = base + l;
        float dt_v = g_dt[(size_t)r * D_INNER + d];
        float u_v  = g_u [(size_t)r * D_INNER + d];
        float Bn = g_dbl[r * 96 + DT_RANK + n];
        float Cn = g_dbl[r * 96 + DT_RANK + D_STATE + n];
        h = fmaf(__expf(dt_v * An), h, dt_v * Bn * u_v);
        float p = h * Cn;
        #pragma unroll
        for (int o = 8; o > 0; o >>= 1)
            p += __shfl_xor_sync(0xffffffffu, p, o);
        if (n == 0) {
            float zv = g_xz[(size_t)r * (2 * D_INNER) + D_INNER + d];
            float yv = (p + u_v * Dd) * (zv / (1.f + __expf(-zv)));
            g_y[(size_t)r * D_INNER + d] = yv;
        }
    }
}

// ---------------- launch ----------------
static inline dim3 gemm_grid(int M, int N) {
    return dim3((N + 127) / 128, (M + 127) / 128);
}

extern "C" void kernel_launch(void* const* d_in, const int* in_sizes, int n_in,
                              void* d_out, int out_size) {
    const int*   tokens    = (const int*)  d_in[0];
    const float* embedding = (const float*)d_in[1];
    const float* norm_w    = (const float*)d_in[2];
    const float* in_proj   = (const float*)d_in[3];
    const float* conv_w    = (const float*)d_in[4];
    const float* conv_b    = (const float*)d_in[5];
    const float* x_proj    = (const float*)d_in[6];
    const float* dt_w      = (const float*)d_in[7];
    const float* dt_b      = (const float*)d_in[8];
    const float* A_log     = (const float*)d_in[9];
    const float* Dp        = (const float*)d_in[10];
    const float* out_proj  = (const float*)d_in[11];
    const float* fnorm_w   = (const float*)d_in[12];
    const float* head_w    = (const float*)d_in[13];
    float* out = (float*)d_out;

    float *px, *pxn, *pxz, *pu, *pdbl, *pdt, *py;
    cudaGetSymbolAddress((void**)&px,  g_x);
    cudaGetSymbolAddress((void**)&pxn, g_xn);
    cudaGetSymbolAddress((void**)&pxz, g_xz);
    cudaGetSymbolAddress((void**)&pu,  g_u);
    cudaGetSymbolAddress((void**)&pdbl,g_dbl);
    cudaGetSymbolAddress((void**)&pdt, g_dt);
    cudaGetSymbolAddress((void**)&py,  g_y);

    embed_kernel<<<(ROWS * D_MODEL + 255) / 256, 256>>>(tokens, embedding);

    for (int i = 0; i < N_LAYER; i++) {
        const float* w_norm = norm_w   + (size_t)i * D_MODEL;
        const float* w_in   = in_proj  + (size_t)i * D_MODEL * 2 * D_INNER;
        const float* w_cw   = conv_w   + (size_t)i * D_INNER * D_CONV;
        const float* w_cb   = conv_b   + (size_t)i * D_INNER;
        const float* w_xp   = x_proj   + (size_t)i * D_INNER * (DT_RANK + 2 * D_STATE);
        const float* w_dtw  = dt_w     + (size_t)i * DT_RANK * D_INNER;
        const float* w_dtb  = dt_b     + (size_t)i * D_INNER;
        const float* w_Alog = A_log    + (size_t)i * D_INNER * D_STATE;
        const float* w_D    = Dp       + (size_t)i * D_INNER;
        const float* w_out  = out_proj + (size_t)i * D_INNER * D_MODEL;

        rmsnorm_kernel<<<ROWS, 256>>>(px, w_norm, pxn);

        // xz = xn @ in_proj : [2048,1024] x [1024,4096]
        sgemm_kernel<0><<<gemm_grid(ROWS, 2 * D_INNER), 256>>>(
            ROWS, 2 * D_INNER, D_MODEL, pxn, D_MODEL, w_in, 2 * D_INNER,
            pxz, 2 * D_INNER, nullptr);

        conv_silu_kernel<<<(ROWS * D_INNER + 255) / 256, 256>>>(w_cw, w_cb);

        // dbl = u @ x_proj : [2048,2048] x [2048,96]
        sgemm_kernel<0><<<gemm_grid(ROWS, 96), 256>>>(
            ROWS, 96, D_INNER, pu, D_INNER, w_xp, 96, pdbl, 96, nullptr);

        // dt = softplus(dbl[:, :64] @ dt_w + dt_b) : [2048,64] x [64,2048]
        sgemm_kernel<1><<<gemm_grid(ROWS, D_INNER), 256>>>(
            ROWS, D_INNER, DT_RANK, pdbl, 96, w_dtw, D_INNER,
            pdt, D_INNER, w_dtb);

        // selective scan (+ u*D + silu(z) gating fused)
        scan_kernel<<<256, 256>>>(w_Alog, w_D);

        // x = y @ out_proj + x : [2048,2048] x [2048,1024]
        sgemm_kernel<2><<<gemm_grid(ROWS, D_MODEL), 256>>>(
            ROWS, D_MODEL, D_INNER, py, D_INNER, w_out, D_MODEL,
            px, D_MODEL, px);
    }

    rmsnorm_kernel<<<ROWS, 256>>>(px, fnorm_w, pxn);

    // logits = xn @ head_w : [2048,1024] x [1024,32000]
    sgemm_kernel<0><<<gemm_grid(ROWS, VOCAB), 256>>>(
        ROWS, VOCAB, D_MODEL, pxn, D_MODEL, head_w, VOCAB,
        out, VOCAB, nullptr);
}

// round 5
// speedup vs baseline: 1.7478x; 1.7478x over previous
#include <cuda_runtime.h>
#include <cuda_bf16.h>
#include <cstdint>

#define D_MODEL 1024
#define D_INNER 2048
#define D_STATE 16
#define DT_RANK 64
#define D_CONV  4
#define N_LAYER 4
#define VOCAB   32000
#define Bb      2
#define Ll      1024
#define ROWS    (Bb * Ll)   // 2048

// ---------------- scratch (static device arrays; no allocs) ----------------
__device__ float g_x [ROWS * D_MODEL];       // residual stream
__device__ float g_xn[ROWS * D_MODEL];       // normed
__device__ float g_xz[ROWS * 2 * D_INNER];   // in_proj output (u|z)
__device__ float g_u [ROWS * D_INNER];       // conv+silu output
__device__ float g_dbl[ROWS * (DT_RANK + 2 * D_STATE)]; // x_proj output (96)
__device__ float g_dt[ROWS * D_INNER];       // softplus(dt)
__device__ float g_y [ROWS * D_INNER];       // scan output (gated)

// bf16 hi/lo split scratch for tensor-core GEMMs (weights stored [N,K])
__device__ __nv_bfloat16 g_win_h [N_LAYER * 2 * D_INNER * D_MODEL];
__device__ __nv_bfloat16 g_win_l [N_LAYER * 2 * D_INNER * D_MODEL];
__device__ __nv_bfloat16 g_wout_h[N_LAYER * D_MODEL * D_INNER];
__device__ __nv_bfloat16 g_wout_l[N_LAYER * D_MODEL * D_INNER];
__device__ __nv_bfloat16 g_whd_h [VOCAB * D_MODEL];
__device__ __nv_bfloat16 g_whd_l [VOCAB * D_MODEL];
__device__ __nv_bfloat16 g_ah[ROWS * D_INNER];    // activation hi
__device__ __nv_bfloat16 g_al[ROWS * D_INNER];    // activation lo

// ---------------- PTX helpers ----------------
__device__ __forceinline__ uint32_t smem_u32(const void* p) {
    uint32_t a;
    asm("{ .reg .u64 t; cvta.to.shared.u64 t, %1; cvt.u32.u64 %0, t; }"
        : "=r"(a) : "l"(p));
    return a;
}
__device__ __forceinline__ void cp16(uint32_t s, const void* g) {
    asm volatile("cp.async.cg.shared.global [%0], [%1], 16;\n"
                 :: "r"(s), "l"(__cvta_generic_to_global(g)) : "memory");
}
__device__ __forceinline__ void ldm_x4(uint32_t a, uint32_t* r) {
    asm volatile("ldmatrix.sync.aligned.m8n8.x4.shared.b16 {%0,%1,%2,%3}, [%4];"
                 : "=r"(r[0]), "=r"(r[1]), "=r"(r[2]), "=r"(r[3]) : "r"(a));
}
__device__ __forceinline__ void ldm_x2(uint32_t a, uint32_t* r) {
    asm volatile("ldmatrix.sync.aligned.m8n8.x2.shared.b16 {%0,%1}, [%2];"
                 : "=r"(r[0]), "=r"(r[1]) : "r"(a));
}
__device__ __forceinline__ void mma16816(float* c, const uint32_t* a, const uint32_t* b) {
    asm volatile(
        "mma.sync.aligned.m16n8k16.row.col.f32.bf16.bf16.f32 "
        "{%0,%1,%2,%3},{%4,%5,%6,%7},{%8,%9},{%0,%1,%2,%3};"
        : "+f"(c[0]), "+f"(c[1]), "+f"(c[2]), "+f"(c[3])
        : "r"(a[0]), "r"(a[1]), "r"(a[2]), "r"(a[3]), "r"(b[0]), "r"(b[1]));
}

// ---------------- HMMA GEMM: C[M,N] = A[M,K] * Bt[N,K]^T (+epilogue) -------
// A/B bf16 K-major hi+lo split; 3-term product for ~fp32 accuracy.
// EPI 0: plain store    EPI 2: add residual aux[row*ldc+col]
// CTA tile 128x128, BK=32, 8 warps (2x4), warp tile 64x32, 3-stage cp.async.
#define ROWB   80                           // smem row stride in bytes (32 bf16 + 16B pad)
#define BUFB   (128 * ROWB)                 // 10240 B per operand buffer
#define STAGEB (4 * BUFB)                   // 40960 B per stage (Ah,Al,Bh,Bl)
#define NSTG   3
#define GEMM_SMEM (NSTG * STAGEB)           // 122880 B

template <int EPI>
__global__ __launch_bounds__(256, 1)
void hmma_gemm_kernel(int M, int N, int K,
                      const __nv_bfloat16* __restrict__ Ah,
                      const __nv_bfloat16* __restrict__ Al,
                      const __nv_bfloat16* __restrict__ Bh,
                      const __nv_bfloat16* __restrict__ Bl,
                      float* __restrict__ C, int ldc,
                      const float* __restrict__ aux) {
    extern __shared__ char smem[];
    const uint32_t sb = smem_u32(smem);
    const int tid  = threadIdx.x;
    const int lane = tid & 31;
    const int w    = tid >> 5;
    const int wm   = w >> 2;        // 0..1
    const int wn   = w & 3;         // 0..3
    const int rowA = blockIdx.x * 128;
    const int colC = blockIdx.y * 128;

    // gmem row pointers for this thread's two (row,chunk) pairs per buffer
    // idx = tid + t*256 ; row = idx>>2 ; chunk = idx&3
    const int r0 = tid >> 2,  c0 = tid & 3;
    const int r1 = (tid + 256) >> 2, c1 = tid & 3; // (tid+256)&3 == tid&3

    const int kiters = K >> 5;   // BK=32

    auto load_stage = [&](int it) {
        const uint32_t st = sb + (uint32_t)(it % NSTG) * STAGEB;
        const int k0 = it << 5;
        const __nv_bfloat16* gA_h = Ah + (size_t)(rowA + r0) * K + k0 + c0 * 8;
        const __nv_bfloat16* gA_l = Al + (size_t)(rowA + r0) * K + k0 + c0 * 8;
        const __nv_bfloat16* gB_h = Bh + (size_t)(colC + r0) * K + k0 + c0 * 8;
        const __nv_bfloat16* gB_l = Bl + (size_t)(colC + r0) * K + k0 + c0 * 8;
        const uint32_t so0 = (uint32_t)r0 * ROWB + c0 * 16;
        cp16(st +            so0, gA_h);
        cp16(st + BUFB     + so0, gA_l);
        cp16(st + 2 * BUFB + so0, gB_h);
        cp16(st + 3 * BUFB + so0, gB_l);
        const __nv_bfloat16* gA_h2 = Ah + (size_t)(rowA + r1) * K + k0 + c1 * 8;
        const __nv_bfloat16* gA_l2 = Al + (size_t)(rowA + r1) * K + k0 + c1 * 8;
        const __nv_bfloat16* gB_h2 = Bh + (size_t)(colC + r1) * K + k0 + c1 * 8;
        const __nv_bfloat16* gB_l2 = Bl + (size_t)(colC + r1) * K + k0 + c1 * 8;
        const uint32_t so1 = (uint32_t)r1 * ROWB + c1 * 16;
        cp16(st +            so1, gA_h2);
        cp16(st + BUFB     + so1, gA_l2);
        cp16(st + 2 * BUFB + so1, gB_h2);
        cp16(st + 3 * BUFB + so1, gB_l2);
        asm volatile("cp.async.commit_group;" ::: "memory");
    };

    float acc[4][4][4];
    #pragma unroll
    for (int m = 0; m < 4; m++)
        #pragma unroll
        for (int n = 0; n < 4; n++)
            #pragma unroll
            for (int e = 0; e < 4; e++) acc[m][n][e] = 0.f;

    load_stage(0);
    if (kiters > 1) load_stage(1);

    // ldmatrix per-lane address components
    const int ar = lane & 15;                   // A row within 16
    const int ac = (lane >> 4) << 3;            // A col offset (elements)
    const int br = lane & 7;                    // B row within 8
    const int bc = ((lane >> 3) & 1) << 3;      // B col offset (x2 uses lanes 0-15)

    for (int i = 0; i < kiters; i++) {
        if (i + 1 < kiters) asm volatile("cp.async.wait_group 1;" ::: "memory");
        else                asm volatile("cp.async.wait_group 0;" ::: "memory");
        __syncthreads();
        if (i + 2 < kiters) load_stage(i + 2);

        const uint32_t st = sb + (uint32_t)(i % NSTG) * STAGEB;
        #pragma unroll
        for (int kk = 0; kk < 32; kk += 16) {
            uint32_t ah[4][4], al[4][4], bh[4][2], bl[4][2];
            #pragma unroll
            for (int m = 0; m < 4; m++) {
                uint32_t adr = st + (uint32_t)(wm * 64 + m * 16 + ar) * ROWB
                                  + (kk + ac) * 2;
                ldm_x4(adr, ah[m]);
                ldm_x4(adr + BUFB, al[m]);
            }
            #pragma unroll
            for (int n = 0; n < 4; n++) {
                uint32_t adr = st + 2 * BUFB
                                  + (uint32_t)(wn * 32 + n * 8 + br) * ROWB
                                  + (kk + bc) * 2;
                ldm_x2(adr, bh[n]);
                ldm_x2(adr + BUFB, bl[n]);
            }
            #pragma unroll
            for (int m = 0; m < 4; m++)
                #pragma unroll
                for (int n = 0; n < 4; n++) {
                    mma16816(acc[m][n], ah[m], bh[n]);
                    mma16816(acc[m][n], ah[m], bl[n]);
                    mma16816(acc[m][n], al[m], bh[n]);
                }
        }
        __syncthreads();
    }

    // epilogue: thread holds (row=lane/4, col=2*(lane%4)) quads per 16x8 tile
    const int er = lane >> 2;
    const int ec = (lane & 3) * 2;
    #pragma unroll
    for (int m = 0; m < 4; m++) {
        const int grow = rowA + wm * 64 + m * 16 + er;
        #pragma unroll
        for (int n = 0; n < 4; n++) {
            const int gcol = colC + wn * 32 + n * 8 + ec;
            float2 v0 = make_float2(acc[m][n][0], acc[m][n][1]);
            float2 v1 = make_float2(acc[m][n][2], acc[m][n][3]);
            if (EPI == 2) {
                float2 a0 = *reinterpret_cast<const float2*>(
                    aux + (size_t)grow * ldc + gcol);
                float2 a1 = *reinterpret_cast<const float2*>(
                    aux + (size_t)(grow + 8) * ldc + gcol);
                v0.x += a0.x; v0.y += a0.y;
                v1.x += a1.x; v1.y += a1.y;
            }
            *reinterpret_cast<float2*>(C + (size_t)grow * ldc + gcol) = v0;
            *reinterpret_cast<float2*>(C + (size_t)(grow + 8) * ldc + gcol) = v1;
        }
    }
}

// ---------------- transpose + bf16 split: in[R,C] -> out hi/lo [C,R] -------
__global__ void tsplit_kernel(const float* __restrict__ in,
                              __nv_bfloat16* __restrict__ oh,
                              __nv_bfloat16* __restrict__ ol, int R, int Ccols) {
    __shared__ float t[32][33];
    int rb = blockIdx.x * 32, cb = blockIdx.y * 32;
    int x = threadIdx.x, y = threadIdx.y;  // (32,8)
    #pragma unroll
    for (int j = 0; j < 4; j++)
        t[y + 8 * j][x] = in[(size_t)(rb + y + 8 * j) * Ccols + cb + x];
    __syncthreads();
    #pragma unroll
    for (int j = 0; j < 4; j++) {
        float v = t[x][y + 8 * j];
        __nv_bfloat16 h = __float2bfloat16(v);
        __nv_bfloat16 l = __float2bfloat16(v - __bfloat162float(h));
        size_t o = (size_t)(cb + y + 8 * j) * R + rb + x;
        oh[o] = h; ol[o] = l;
    }
}

// ---------------- elementwise bf16 split ----------------
__global__ void split_kernel(const float* __restrict__ in,
                             __nv_bfloat16* __restrict__ oh,
                             __nv_bfloat16* __restrict__ ol, int n) {
    int i = blockIdx.x * blockDim.x + threadIdx.x;
    if (i >= n) return;
    float v = in[i];
    __nv_bfloat16 h = __float2bfloat16(v);
    oh[i] = h;
    ol[i] = __float2bfloat16(v - __bfloat162float(h));
}

// ---------------- embedding gather ----------------
__global__ void embed_kernel(const int* __restrict__ tokens,
                             const float* __restrict__ emb) {
    int idx = blockIdx.x * blockDim.x + threadIdx.x;
    if (idx >= ROWS * D_MODEL) return;
    int row = idx / D_MODEL;
    int c   = idx % D_MODEL;
    g_x[idx] = emb[tokens[row] * D_MODEL + c];
}

// ---------------- rmsnorm: one block per row ----------------
__global__ void rmsnorm_kernel(const float* __restrict__ in,
                               const float* __restrict__ w,
                               float* __restrict__ out) {
    __shared__ float red[8];
    int row = blockIdx.x;
    const float* x = in + row * D_MODEL;
    const float4* x4 = reinterpret_cast<const float4*>(x);
    float4 v = x4[threadIdx.x];
    float s = v.x * v.x + v.y * v.y + v.z * v.z + v.w * v.w;
    #pragma unroll
    for (int o = 16; o > 0; o >>= 1) s += __shfl_xor_sync(0xffffffffu, s, o);
    if ((threadIdx.x & 31) == 0) red[threadIdx.x >> 5] = s;
    __syncthreads();
    if (threadIdx.x < 8) {
        float t = red[threadIdx.x];
        #pragma unroll
        for (int o = 4; o > 0; o >>= 1) t += __shfl_xor_sync(0xffu, t, o);
        if (threadIdx.x == 0) red[0] = t;
    }
    __syncthreads();
    float rs = rsqrtf(red[0] * (1.0f / D_MODEL) + 1e-5f);
    const float4* w4 = reinterpret_cast<const float4*>(w);
    float4 wv = w4[threadIdx.x];
    float4 o4;
    o4.x = v.x * rs * wv.x; o4.y = v.y * rs * wv.y;
    o4.z = v.z * rs * wv.z; o4.w = v.w * rs * wv.w;
    reinterpret_cast<float4*>(out + row * D_MODEL)[threadIdx.x] = o4;
}

// ---------------- generic SGEMM (small GEMMs only) ----------------
// EPI 0: plain  EPI 1: softplus(acc + bias[col])
template <int EPI>
__global__ __launch_bounds__(256)
void sgemm_kernel(int M, int N, int K,
                  const float* __restrict__ A, int lda,
                  const float* __restrict__ B, int ldb,
                  float* __restrict__ C, int ldc,
                  const float* __restrict__ aux) {
    constexpr int BM = 128, BN = 128, BK = 8, TM = 8, TN = 8;
    __shared__ float As[BK][BM];
    __shared__ float Bs[BK][BN];
    int tid = threadIdx.x;
    int blockRow = blockIdx.y * BM;
    int blockCol = blockIdx.x * BN;
    int tr = tid / 16;
    int tc = tid % 16;

    float acc[TM][TN];
    #pragma unroll
    for (int i = 0; i < TM; i++)
        #pragma unroll
        for (int j = 0; j < TN; j++) acc[i][j] = 0.f;

    for (int k0 = 0; k0 < K; k0 += BK) {
        #pragma unroll
        for (int i = 0; i < 4; i++) {
            int idx = tid + i * 256;
            int r = idx / BK, c = idx % BK;
            int gr = blockRow + r, gc = k0 + c;
            As[c][r] = (gr < M && gc < K) ? A[gr * lda + gc] : 0.f;
        }
        #pragma unroll
        for (int i = 0; i < 4; i++) {
            int idx = tid + i * 256;
            int r = idx / BN, c = idx % BN;
            int gr = k0 + r, gc = blockCol + c;
            Bs[r][c] = (gr < K && gc < N) ? B[gr * ldb + gc] : 0.f;
        }
        __syncthreads();
        #pragma unroll
        for (int k = 0; k < BK; k++) {
            float ra[TM], rb[TN];
            float4 a0 = reinterpret_cast<float4*>(&As[k][tr * TM])[0];
            float4 a1 = reinterpret_cast<float4*>(&As[k][tr * TM])[1];
            ra[0] = a0.x; ra[1] = a0.y; ra[2] = a0.z; ra[3] = a0.w;
            ra[4] = a1.x; ra[5] = a1.y; ra[6] = a1.z; ra[7] = a1.w;
            float4 b0 = reinterpret_cast<float4*>(&Bs[k][tc * TN])[0];
            float4 b1 = reinterpret_cast<float4*>(&Bs[k][tc * TN])[1];
            rb[0] = b0.x; rb[1] = b0.y; rb[2] = b0.z; rb[3] = b0.w;
            rb[4] = b1.x; rb[5] = b1.y; rb[6] = b1.z; rb[7] = b1.w;
            #pragma unroll
            for (int i = 0; i < TM; i++)
                #pragma unroll
                for (int j = 0; j < TN; j++)
                    acc[i][j] = fmaf(ra[i], rb[j], acc[i][j]);
        }
        __syncthreads();
    }

    #pragma unroll
    for (int i = 0; i < TM; i++) {
        int gr = blockRow + tr * TM + i;
        if (gr >= M) continue;
        #pragma unroll
        for (int j = 0; j < TN; j++) {
            int gc = blockCol + tc * TN + j;
            if (gc >= N) continue;
            float v = acc[i][j];
            if (EPI == 1) {
                v += aux[gc];
                v = (v > 20.f) ? v : log1pf(__expf(v));
            }
            C[gr * ldc + gc] = v;
        }
    }
}

// ---------------- depthwise causal conv1d + silu ----------------
__global__ void conv_silu_kernel(const float* __restrict__ conv_w,
                                 const float* __restrict__ conv_b) {
    int idx = blockIdx.x * blockDim.x + threadIdx.x;
    if (idx >= ROWS * D_INNER) return;
    int d = idx % D_INNER;
    int row = idx / D_INNER;
    int l = row % Ll;
    int rowbase = row - l;
    float acc = conv_b[d];
    #pragma unroll
    for (int k = 0; k < D_CONV; k++) {
        int ll = l - (D_CONV - 1) + k;
        if (ll >= 0)
            acc = fmaf(conv_w[d * D_CONV + k],
                       g_xz[(size_t)(rowbase + ll) * (2 * D_INNER) + d], acc);
    }
    g_u[idx] = acc / (1.f + __expf(-acc));
}

// ---------------- selective scan ----------------
__global__ void scan_kernel(const float* __restrict__ A_log,
                            const float* __restrict__ Dp) {
    int warp = (blockIdx.x * blockDim.x + threadIdx.x) >> 5;
    int lane = threadIdx.x & 31;
    int n = lane & 15;
    int ch = warp * 2 + (lane >> 4);
    if (ch >= Bb * D_INNER) return;
    int b = ch / D_INNER;
    int d = ch % D_INNER;

    float An = -__expf(A_log[d * D_STATE + n]);
    float Dd = Dp[d];
    float h = 0.f;

    int base = b * Ll;
    for (int l = 0; l < Ll; l++) {
        int r = base + l;
        float dt_v = g_dt[(size_t)r * D_INNER + d];
        float u_v  = g_u [(size_t)r * D_INNER + d];
        float Bn = g_dbl[r * 96 + DT_RANK + n];
        float Cn = g_dbl[r * 96 + DT_RANK + D_STATE + n];
        h = fmaf(__expf(dt_v * An), h, dt_v * Bn * u_v);
        float p = h * Cn;
        #pragma unroll
        for (int o = 8; o > 0; o >>= 1)
            p += __shfl_xor_sync(0xffffffffu, p, o);
        if (n == 0) {
            float zv = g_xz[(size_t)r * (2 * D_INNER) + D_INNER + d];
            float yv = (p + u_v * Dd) * (zv / (1.f + __expf(-zv)));
            g_y[(size_t)r * D_INNER + d] = yv;
        }
    }
}

// ---------------- launch ----------------
extern "C" void kernel_launch(void* const* d_in, const int* in_sizes, int n_in,
                              void* d_out, int out_size) {
    const int*   tokens    = (const int*)  d_in[0];
    const float* embedding = (const float*)d_in[1];
    const float* norm_w    = (const float*)d_in[2];
    const float* in_proj   = (const float*)d_in[3];
    const float* conv_w    = (const float*)d_in[4];
    const float* conv_b    = (const float*)d_in[5];
    const float* x_proj    = (const float*)d_in[6];
    const float* dt_w      = (const float*)d_in[7];
    const float* dt_b      = (const float*)d_in[8];
    const float* A_log     = (const float*)d_in[9];
    const float* Dp        = (const float*)d_in[10];
    const float* out_proj  = (const float*)d_in[11];
    const float* fnorm_w   = (const float*)d_in[12];
    const float* head_w    = (const float*)d_in[13];
    float* out = (float*)d_out;

    float *px, *pxn, *pxz, *pu, *pdbl, *pdt, *py;
    cudaGetSymbolAddress((void**)&px,  g_x);
    cudaGetSymbolAddress((void**)&pxn, g_xn);
    cudaGetSymbolAddress((void**)&pxz, g_xz);
    cudaGetSymbolAddress((void**)&pu,  g_u);
    cudaGetSymbolAddress((void**)&pdbl,g_dbl);
    cudaGetSymbolAddress((void**)&pdt, g_dt);
    cudaGetSymbolAddress((void**)&py,  g_y);

    __nv_bfloat16 *pwin_h, *pwin_l, *pwout_h, *pwout_l, *phd_h, *phd_l, *pah, *pal;
    cudaGetSymbolAddress((void**)&pwin_h,  g_win_h);
    cudaGetSymbolAddress((void**)&pwin_l,  g_win_l);
    cudaGetSymbolAddress((void**)&pwout_h, g_wout_h);
    cudaGetSymbolAddress((void**)&pwout_l, g_wout_l);
    cudaGetSymbolAddress((void**)&phd_h,   g_whd_h);
    cudaGetSymbolAddress((void**)&phd_l,   g_whd_l);
    cudaGetSymbolAddress((void**)&pah,     g_ah);
    cudaGetSymbolAddress((void**)&pal,     g_al);

    cudaFuncSetAttribute(hmma_gemm_kernel<0>,
                         cudaFuncAttributeMaxDynamicSharedMemorySize, GEMM_SMEM);
    cudaFuncSetAttribute(hmma_gemm_kernel<2>,
                         cudaFuncAttributeMaxDynamicSharedMemorySize, GEMM_SMEM);

    dim3 tsB(32, 8);

    // weight transpose + split (every launch; deterministic, bandwidth-cheap)
    for (int i = 0; i < N_LAYER; i++) {
        tsplit_kernel<<<dim3(D_MODEL / 32, (2 * D_INNER) / 32), tsB>>>(
            in_proj + (size_t)i * D_MODEL * 2 * D_INNER,
            pwin_h + (size_t)i * 2 * D_INNER * D_MODEL,
            pwin_l + (size_t)i * 2 * D_INNER * D_MODEL, D_MODEL, 2 * D_INNER);
        tsplit_kernel<<<dim3(D_INNER / 32, D_MODEL / 32), tsB>>>(
            out_proj + (size_t)i * D_INNER * D_MODEL,
            pwout_h + (size_t)i * D_MODEL * D_INNER,
            pwout_l + (size_t)i * D_MODEL * D_INNER, D_INNER, D_MODEL);
    }
    tsplit_kernel<<<dim3(D_MODEL / 32, VOCAB / 32), tsB>>>(
        head_w, phd_h, phd_l, D_MODEL, VOCAB);

    embed_kernel<<<(ROWS * D_MODEL + 255) / 256, 256>>>(tokens, embedding);

    for (int i = 0; i < N_LAYER; i++) {
        const float* w_norm = norm_w   + (size_t)i * D_MODEL;
        const float* w_cw   = conv_w   + (size_t)i * D_INNER * D_CONV;
        const float* w_cb   = conv_b   + (size_t)i * D_INNER;
        const float* w_xp   = x_proj   + (size_t)i * D_INNER * (DT_RANK + 2 * D_STATE);
        const float* w_dtw  = dt_w     + (size_t)i * DT_RANK * D_INNER;
        const float* w_dtb  = dt_b     + (size_t)i * D_INNER;
        const float* w_Alog = A_log    + (size_t)i * D_INNER * D_STATE;
        const float* w_D    = Dp       + (size_t)i * D_INNER;

        rmsnorm_kernel<<<ROWS, 256>>>(px, w_norm, pxn);

        // xz = xn @ in_proj : HMMA [2048,4096,1024]
        split_kernel<<<(ROWS * D_MODEL + 255) / 256, 256>>>(pxn, pah, pal, ROWS * D_MODEL);
        hmma_gemm_kernel<0><<<dim3(ROWS / 128, (2 * D_INNER) / 128), 256, GEMM_SMEM>>>(
            ROWS, 2 * D_INNER, D_MODEL, pah, pal,
            pwin_h + (size_t)i * 2 * D_INNER * D_MODEL,
            pwin_l + (size_t)i * 2 * D_INNER * D_MODEL,
            pxz, 2 * D_INNER, nullptr);

        conv_silu_kernel<<<(ROWS * D_INNER + 255) / 256, 256>>>(w_cw, w_cb);

        // dbl = u @ x_proj (fp32 SIMT, N=96)
        sgemm_kernel<0><<<dim3(1, ROWS / 128), 256>>>(
            ROWS, 96, D_INNER, pu, D_INNER, w_xp, 96, pdbl, 96, nullptr);

        // dt = softplus(dbl[:, :64] @ dt_w + dt_b) (fp32 SIMT, K=64)
        sgemm_kernel<1><<<dim3(D_INNER / 128, ROWS / 128), 256>>>(
            ROWS, D_INNER, DT_RANK, pdbl, 96, w_dtw, D_INNER,
            pdt, D_INNER, w_dtb);

        scan_kernel<<<256, 256>>>(w_Alog, w_D);

        // x = y @ out_proj + x : HMMA [2048,1024,2048] + residual
        split_kernel<<<(ROWS * D_INNER + 255) / 256, 256>>>(py, pah, pal, ROWS * D_INNER);
        hmma_gemm_kernel<2><<<dim3(ROWS / 128, D_MODEL / 128), 256, GEMM_SMEM>>>(
            ROWS, D_MODEL, D_INNER, pah, pal,
            pwout_h + (size_t)i * D_MODEL * D_INNER,
            pwout_l + (size_t)i * D_MODEL * D_INNER,
            px, D_MODEL, px);
    }

    rmsnorm_kernel<<<ROWS, 256>>>(px, fnorm_w, pxn);

    // logits = xn @ head_w : HMMA [2048,32000,1024]
    split_kernel<<<(ROWS * D_MODEL + 255) / 256, 256>>>(pxn, pah, pal, ROWS * D_MODEL);
    hmma_gemm_kernel<0><<<dim3(ROWS / 128, VOCAB / 128), 256, GEMM_SMEM>>>(
        ROWS, VOCAB, D_MODEL, pah, pal, phd_h, phd_l,
        out, VOCAB, nullptr);
}

// round 6
// speedup vs baseline: 2.0051x; 1.1472x over previous
#include <cuda_runtime.h>
#include <cuda_bf16.h>
#include <cstdint>

#define D_MODEL 1024
#define D_INNER 2048
#define D_STATE 16
#define DT_RANK 64
#define D_CONV  4
#define N_LAYER 4
#define VOCAB   32000
#define Bb      2
#define Ll      1024
#define ROWS    (Bb * Ll)   // 2048
#define XP_N    96          // DT_RANK + 2*D_STATE
#define XP_NPAD 128

// ---------------- scratch (static device arrays; no allocs) ----------------
__device__ float g_x  [ROWS * D_MODEL];       // residual stream
__device__ float g_xz [ROWS * 2 * D_INNER];   // in_proj output (u|z)
__device__ float g_u  [ROWS * D_INNER];       // conv+silu output (fp32, scan input)
__device__ float g_dbl[ROWS * XP_N];          // x_proj output
__device__ float g_dt [ROWS * D_INNER];       // softplus(dt)

// bf16 hi/lo split scratch (weights stored [N,K])
__device__ __nv_bfloat16 g_win_h [N_LAYER * 2 * D_INNER * D_MODEL];
__device__ __nv_bfloat16 g_win_l [N_LAYER * 2 * D_INNER * D_MODEL];
__device__ __nv_bfloat16 g_wout_h[N_LAYER * D_MODEL * D_INNER];
__device__ __nv_bfloat16 g_wout_l[N_LAYER * D_MODEL * D_INNER];
__device__ __nv_bfloat16 g_wxp_h [N_LAYER * XP_NPAD * D_INNER];  // rows 96..127 stay zero
__device__ __nv_bfloat16 g_wxp_l [N_LAYER * XP_NPAD * D_INNER];
__device__ __nv_bfloat16 g_whd_h [VOCAB * D_MODEL];
__device__ __nv_bfloat16 g_whd_l [VOCAB * D_MODEL];
__device__ __nv_bfloat16 g_ah[ROWS * D_INNER];    // activation hi (reused per stage)
__device__ __nv_bfloat16 g_al[ROWS * D_INNER];    // activation lo

// ---------------- PTX helpers ----------------
__device__ __forceinline__ uint32_t smem_u32(const void* p) {
    uint32_t a;
    asm("{ .reg .u64 t; cvta.to.shared.u64 t, %1; cvt.u32.u64 %0, t; }"
        : "=r"(a) : "l"(p));
    return a;
}
__device__ __forceinline__ void cp16(uint32_t s, const void* g) {
    asm volatile("cp.async.cg.shared.global [%0], [%1], 16;\n"
                 :: "r"(s), "l"(__cvta_generic_to_global(g)) : "memory");
}
__device__ __forceinline__ void ldm_x4(uint32_t a, uint32_t* r) {
    asm volatile("ldmatrix.sync.aligned.m8n8.x4.shared.b16 {%0,%1,%2,%3}, [%4];"
                 : "=r"(r[0]), "=r"(r[1]), "=r"(r[2]), "=r"(r[3]) : "r"(a));
}
__device__ __forceinline__ void ldm_x2(uint32_t a, uint32_t* r) {
    asm volatile("ldmatrix.sync.aligned.m8n8.x2.shared.b16 {%0,%1}, [%2];"
                 : "=r"(r[0]), "=r"(r[1]) : "r"(a));
}
__device__ __forceinline__ void mma16816(float* c, const uint32_t* a, const uint32_t* b) {
    asm volatile(
        "mma.sync.aligned.m16n8k16.row.col.f32.bf16.bf16.f32 "
        "{%0,%1,%2,%3},{%4,%5,%6,%7},{%8,%9},{%0,%1,%2,%3};"
        : "+f"(c[0]), "+f"(c[1]), "+f"(c[2]), "+f"(c[3])
        : "r"(a[0]), "r"(a[1]), "r"(a[2]), "r"(a[3]), "r"(b[0]), "r"(b[1]));
}
__device__ __forceinline__ void split1(float v, __nv_bfloat16* oh, __nv_bfloat16* ol) {
    __nv_bfloat16 h = __float2bfloat16(v);
    *oh = h;
    *ol = __float2bfloat16(v - __bfloat162float(h));
}

// ---------------- HMMA GEMM: C[M,N] = A[M,K] * Bt[N,K]^T (+epilogue) -------
// A/B bf16 K-major hi+lo split; 3-term product (AhBh+AhBl+AlBh) ~fp32 accuracy.
// EPI 0: plain   EPI 2: +residual aux[row*ldc+col].   N may be < 128 (guarded).
#define ROWB   80
#define BUFB   (128 * ROWB)
#define STAGEB (4 * BUFB)
#define NSTG   3
#define GEMM_SMEM (NSTG * STAGEB)     // 122880 B

template <int EPI>
__global__ __launch_bounds__(256, 1)
void hmma_gemm_kernel(int M, int N, int K, int lda, int ldb,
                      const __nv_bfloat16* __restrict__ Ah,
                      const __nv_bfloat16* __restrict__ Al,
                      const __nv_bfloat16* __restrict__ Bh,
                      const __nv_bfloat16* __restrict__ Bl,
                      float* __restrict__ C, int ldc,
                      const float* __restrict__ aux) {
    extern __shared__ char smem[];
    const uint32_t sb = smem_u32(smem);
    const int tid  = threadIdx.x;
    const int lane = tid & 31;
    const int w    = tid >> 5;
    const int wm   = w >> 2;
    const int wn   = w & 3;
    const int rowA = blockIdx.x * 128;
    const int colC = blockIdx.y * 128;

    const int r0 = tid >> 2,          c0 = tid & 3;
    const int r1 = (tid + 256) >> 2;  // same chunk c0

    const int kiters = K >> 5;

    auto load_stage = [&](int it) {
        const uint32_t st = sb + (uint32_t)(it % NSTG) * STAGEB;
        const int k0 = it << 5;
        const uint32_t so0 = (uint32_t)r0 * ROWB + c0 * 16;
        const uint32_t so1 = (uint32_t)r1 * ROWB + c0 * 16;
        cp16(st +            so0, Ah + (size_t)(rowA + r0) * lda + k0 + c0 * 8);
        cp16(st + BUFB     + so0, Al + (size_t)(rowA + r0) * lda + k0 + c0 * 8);
        cp16(st + 2 * BUFB + so0, Bh + (size_t)(colC + r0) * ldb + k0 + c0 * 8);
        cp16(st + 3 * BUFB + so0, Bl + (size_t)(colC + r0) * ldb + k0 + c0 * 8);
        cp16(st +            so1, Ah + (size_t)(rowA + r1) * lda + k0 + c0 * 8);
        cp16(st + BUFB     + so1, Al + (size_t)(rowA + r1) * lda + k0 + c0 * 8);
        cp16(st + 2 * BUFB + so1, Bh + (size_t)(colC + r1) * ldb + k0 + c0 * 8);
        cp16(st + 3 * BUFB + so1, Bl + (size_t)(colC + r1) * ldb + k0 + c0 * 8);
        asm volatile("cp.async.commit_group;" ::: "memory");
    };

    float acc[4][4][4];
    #pragma unroll
    for (int m = 0; m < 4; m++)
        #pragma unroll
        for (int n = 0; n < 4; n++)
            #pragma unroll
            for (int e = 0; e < 4; e++) acc[m][n][e] = 0.f;

    load_stage(0);
    if (kiters > 1) load_stage(1);

    const int ar = lane & 15;
    const int ac = (lane >> 4) << 3;
    const int br = lane & 7;
    const int bc = ((lane >> 3) & 1) << 3;

    for (int i = 0; i < kiters; i++) {
        if (i + 1 < kiters) asm volatile("cp.async.wait_group 1;" ::: "memory");
        else                asm volatile("cp.async.wait_group 0;" ::: "memory");
        __syncthreads();
        if (i + 2 < kiters) load_stage(i + 2);

        const uint32_t st = sb + (uint32_t)(i % NSTG) * STAGEB;
        #pragma unroll
        for (int kk = 0; kk < 32; kk += 16) {
            uint32_t ah[4][4], al[4][4], bh[4][2], bl[4][2];
            #pragma unroll
            for (int m = 0; m < 4; m++) {
                uint32_t adr = st + (uint32_t)(wm * 64 + m * 16 + ar) * ROWB
                                  + (kk + ac) * 2;
                ldm_x4(adr, ah[m]);
                ldm_x4(adr + BUFB, al[m]);
            }
            #pragma unroll
            for (int n = 0; n < 4; n++) {
                uint32_t adr = st + 2 * BUFB
                                  + (uint32_t)(wn * 32 + n * 8 + br) * ROWB
                                  + (kk + bc) * 2;
                ldm_x2(adr, bh[n]);
                ldm_x2(adr + BUFB, bl[n]);
            }
            // term-major ordering: 16 independent MMAs between accumulator reuses
            #pragma unroll
            for (int m = 0; m < 4; m++)
                #pragma unroll
                for (int n = 0; n < 4; n++)
                    mma16816(acc[m][n], ah[m], bh[n]);
            #pragma unroll
            for (int m = 0; m < 4; m++)
                #pragma unroll
                for (int n = 0; n < 4; n++)
                    mma16816(acc[m][n], ah[m], bl[n]);
            #pragma unroll
            for (int m = 0; m < 4; m++)
                #pragma unroll
                for (int n = 0; n < 4; n++)
                    mma16816(acc[m][n], al[m], bh[n]);
        }
        __syncthreads();
    }

    const int er = lane >> 2;
    const int ec = (lane & 3) * 2;
    #pragma unroll
    for (int m = 0; m < 4; m++) {
        const int grow = rowA + wm * 64 + m * 16 + er;
        #pragma unroll
        for (int n = 0; n < 4; n++) {
            const int gcol = colC + wn * 32 + n * 8 + ec;
            if (gcol >= N) continue;
            float2 v0 = make_float2(acc[m][n][0], acc[m][n][1]);
            float2 v1 = make_float2(acc[m][n][2], acc[m][n][3]);
            if (EPI == 2) {
                float2 a0 = *reinterpret_cast<const float2*>(
                    aux + (size_t)grow * ldc + gcol);
                float2 a1 = *reinterpret_cast<const float2*>(
                    aux + (size_t)(grow + 8) * ldc + gcol);
                v0.x += a0.x; v0.y += a0.y;
                v1.x += a1.x; v1.y += a1.y;
            }
            *reinterpret_cast<float2*>(C + (size_t)grow * ldc + gcol) = v0;
            *reinterpret_cast<float2*>(C + (size_t)(grow + 8) * ldc + gcol) = v1;
        }
    }
}

// ---------------- transpose + bf16 split: in[R,C] -> out hi/lo [C,R] -------
__global__ void tsplit_kernel(const float* __restrict__ in,
                              __nv_bfloat16* __restrict__ oh,
                              __nv_bfloat16* __restrict__ ol, int R, int Ccols) {
    __shared__ float t[32][33];
    int rb = blockIdx.x * 32, cb = blockIdx.y * 32;
    int x = threadIdx.x, y = threadIdx.y;  // (32,8)
    #pragma unroll
    for (int j = 0; j < 4; j++)
        t[y + 8 * j][x] = in[(size_t)(rb + y + 8 * j) * Ccols + cb + x];
    __syncthreads();
    #pragma unroll
    for (int j = 0; j < 4; j++) {
        float v = t[x][y + 8 * j];
        size_t o = (size_t)(cb + y + 8 * j) * R + rb + x;
        split1(v, oh + o, ol + o);
    }
}

// ---------------- embedding gather ----------------
__global__ void embed_kernel(const int* __restrict__ tokens,
                             const float* __restrict__ emb) {
    int idx = blockIdx.x * blockDim.x + threadIdx.x;
    if (idx >= ROWS * D_MODEL) return;
    int row = idx / D_MODEL;
    int c   = idx % D_MODEL;
    g_x[idx] = emb[tokens[row] * D_MODEL + c];
}

// ---------------- rmsnorm -> bf16 hi/lo directly ----------------
__global__ void rmsnorm_kernel(const float* __restrict__ in,
                               const float* __restrict__ w,
                               __nv_bfloat16* __restrict__ oh,
                               __nv_bfloat16* __restrict__ ol) {
    __shared__ float red[8];
    int row = blockIdx.x;
    const float4* x4 = reinterpret_cast<const float4*>(in + (size_t)row * D_MODEL);
    float4 v = x4[threadIdx.x];
    float s = v.x * v.x + v.y * v.y + v.z * v.z + v.w * v.w;
    #pragma unroll
    for (int o = 16; o > 0; o >>= 1) s += __shfl_xor_sync(0xffffffffu, s, o);
    if ((threadIdx.x & 31) == 0) red[threadIdx.x >> 5] = s;
    __syncthreads();
    if (threadIdx.x < 8) {
        float t = red[threadIdx.x];
        #pragma unroll
        for (int o = 4; o > 0; o >>= 1) t += __shfl_xor_sync(0xffu, t, o);
        if (threadIdx.x == 0) red[0] = t;
    }
    __syncthreads();
    float rs = rsqrtf(red[0] * (1.0f / D_MODEL) + 1e-5f);
    const float4* w4 = reinterpret_cast<const float4*>(w);
    float4 wv = w4[threadIdx.x];
    size_t base = (size_t)row * D_MODEL + threadIdx.x * 4;
    split1(v.x * rs * wv.x, oh + base + 0, ol + base + 0);
    split1(v.y * rs * wv.y, oh + base + 1, ol + base + 1);
    split1(v.z * rs * wv.z, oh + base + 2, ol + base + 2);
    split1(v.w * rs * wv.w, oh + base + 3, ol + base + 3);
}

// ---------------- generic SGEMM (dt projection only) ----------------
// EPI 1: softplus(acc + bias[col])
__global__ __launch_bounds__(256)
void sgemm_sp_kernel(int M, int N, int K,
                     const float* __restrict__ A, int lda,
                     const float* __restrict__ B, int ldb,
                     float* __restrict__ C, int ldc,
                     const float* __restrict__ aux) {
    constexpr int BM = 128, BN = 128, BK = 8, TM = 8, TN = 8;
    __shared__ float As[BK][BM];
    __shared__ float Bs[BK][BN];
    int tid = threadIdx.x;
    int blockRow = blockIdx.y * BM;
    int blockCol = blockIdx.x * BN;
    int tr = tid / 16;
    int tc = tid % 16;

    float acc[TM][TN];
    #pragma unroll
    for (int i = 0; i < TM; i++)
        #pragma unroll
        for (int j = 0; j < TN; j++) acc[i][j] = 0.f;

    for (int k0 = 0; k0 < K; k0 += BK) {
        #pragma unroll
        for (int i = 0; i < 4; i++) {
            int idx = tid + i * 256;
            int r = idx / BK, c = idx % BK;
            As[c][r] = A[(size_t)(blockRow + r) * lda + k0 + c];
        }
        #pragma unroll
        for (int i = 0; i < 4; i++) {
            int idx = tid + i * 256;
            int r = idx / BN, c = idx % BN;
            Bs[r][c] = B[(size_t)(k0 + r) * ldb + blockCol + c];
        }
        __syncthreads();
        #pragma unroll
        for (int k = 0; k < BK; k++) {
            float ra[TM], rb[TN];
            float4 a0 = reinterpret_cast<float4*>(&As[k][tr * TM])[0];
            float4 a1 = reinterpret_cast<float4*>(&As[k][tr * TM])[1];
            ra[0] = a0.x; ra[1] = a0.y; ra[2] = a0.z; ra[3] = a0.w;
            ra[4] = a1.x; ra[5] = a1.y; ra[6] = a1.z; ra[7] = a1.w;
            float4 b0 = reinterpret_cast<float4*>(&Bs[k][tc * TN])[0];
            float4 b1 = reinterpret_cast<float4*>(&Bs[k][tc * TN])[1];
            rb[0] = b0.x; rb[1] = b0.y; rb[2] = b0.z; rb[3] = b0.w;
            rb[4] = b1.x; rb[5] = b1.y; rb[6] = b1.z; rb[7] = b1.w;
            #pragma unroll
            for (int i = 0; i < TM; i++)
                #pragma unroll
                for (int j = 0; j < TN; j++)
                    acc[i][j] = fmaf(ra[i], rb[j], acc[i][j]);
        }
        __syncthreads();
    }

    #pragma unroll
    for (int i = 0; i < TM; i++) {
        int gr = blockRow + tr * TM + i;
        #pragma unroll
        for (int j = 0; j < TN; j++) {
            int gc = blockCol + tc * TN + j;
            float v = acc[i][j] + aux[gc];
            v = (v > 20.f) ? v : log1pf(__expf(v));
            C[(size_t)gr * ldc + gc] = v;
        }
    }
}

// ---------------- depthwise causal conv1d + silu (fp32 + hi/lo) -----------
__global__ void conv_silu_kernel(const float* __restrict__ conv_w,
                                 const float* __restrict__ conv_b) {
    int idx = blockIdx.x * blockDim.x + threadIdx.x;
    if (idx >= ROWS * D_INNER) return;
    int d = idx % D_INNER;
    int row = idx / D_INNER;
    int l = row % Ll;
    int rowbase = row - l;
    float acc = conv_b[d];
    #pragma unroll
    for (int k = 0; k < D_CONV; k++) {
        int ll = l - (D_CONV - 1) + k;
        if (ll >= 0)
            acc = fmaf(conv_w[d * D_CONV + k],
                       g_xz[(size_t)(rowbase + ll) * (2 * D_INNER) + d], acc);
    }
    float s = acc / (1.f + __expf(-acc));
    g_u[idx] = s;
    split1(s, g_ah + idx, g_al + idx);
}

// ---------------- selective scan (writes y hi/lo) ----------------
__global__ void scan_kernel(const float* __restrict__ A_log,
                            const float* __restrict__ Dp) {
    int warp = (blockIdx.x * blockDim.x + threadIdx.x) >> 5;
    int lane = threadIdx.x & 31;
    int n = lane & 15;
    int ch = warp * 2 + (lane >> 4);
    if (ch >= Bb * D_INNER) return;
    int b = ch / D_INNER;
    int d = ch % D_INNER;

    float An = -__expf(A_log[d * D_STATE + n]);
    float Dd = Dp[d];
    float h = 0.f;

    int base = b * Ll;
    for (int l = 0; l < Ll; l++) {
        int r = base + l;
        float dt_v = g_dt[(size_t)r * D_INNER + d];
        float u_v  = g_u [(size_t)r * D_INNER + d];
        float Bn = g_dbl[r * XP_N + DT_RANK + n];
        float Cn = g_dbl[r * XP_N + DT_RANK + D_STATE + n];
        h = fmaf(__expf(dt_v * An), h, dt_v * Bn * u_v);
        float p = h * Cn;
        #pragma unroll
        for (int o = 8; o > 0; o >>= 1)
            p += __shfl_xor_sync(0xffffffffu, p, o);
        if (n == 0) {
            float zv = g_xz[(size_t)r * (2 * D_INNER) + D_INNER + d];
            float yv = (p + u_v * Dd) * (zv / (1.f + __expf(-zv)));
            size_t o = (size_t)r * D_INNER + d;
            split1(yv, g_ah + o, g_al + o);
        }
    }
}

// ---------------- launch ----------------
extern "C" void kernel_launch(void* const* d_in, const int* in_sizes, int n_in,
                              void* d_out, int out_size) {
    const int*   tokens    = (const int*)  d_in[0];
    const float* embedding = (const float*)d_in[1];
    const float* norm_w    = (const float*)d_in[2];
    const float* in_proj   = (const float*)d_in[3];
    const float* conv_w    = (const float*)d_in[4];
    const float* conv_b    = (const float*)d_in[5];
    const float* x_proj    = (const float*)d_in[6];
    const float* dt_w      = (const float*)d_in[7];
    const float* dt_b      = (const float*)d_in[8];
    const float* A_log     = (const float*)d_in[9];
    const float* Dp        = (const float*)d_in[10];
    const float* out_proj  = (const float*)d_in[11];
    const float* fnorm_w   = (const float*)d_in[12];
    const float* head_w    = (const float*)d_in[13];
    float* out = (float*)d_out;

    float *px, *pxz, *pu, *pdbl, *pdt;
    cudaGetSymbolAddress((void**)&px,  g_x);
    cudaGetSymbolAddress((void**)&pxz, g_xz);
    cudaGetSymbolAddress((void**)&pu,  g_u);
    cudaGetSymbolAddress((void**)&pdbl,g_dbl);
    cudaGetSymbolAddress((void**)&pdt, g_dt);

    __nv_bfloat16 *pwin_h, *pwin_l, *pwout_h, *pwout_l, *pwxp_h, *pwxp_l,
                  *phd_h, *phd_l, *pah, *pal;
    cudaGetSymbolAddress((void**)&pwin_h,  g_win_h);
    cudaGetSymbolAddress((void**)&pwin_l,  g_win_l);
    cudaGetSymbolAddress((void**)&pwout_h, g_wout_h);
    cudaGetSymbolAddress((void**)&pwout_l, g_wout_l);
    cudaGetSymbolAddress((void**)&pwxp_h,  g_wxp_h);
    cudaGetSymbolAddress((void**)&pwxp_l,  g_wxp_l);
    cudaGetSymbolAddress((void**)&phd_h,   g_whd_h);
    cudaGetSymbolAddress((void**)&phd_l,   g_whd_l);
    cudaGetSymbolAddress((void**)&pah,     g_ah);
    cudaGetSymbolAddress((void**)&pal,     g_al);

    cudaFuncSetAttribute(hmma_gemm_kernel<0>,
                         cudaFuncAttributeMaxDynamicSharedMemorySize, GEMM_SMEM);
    cudaFuncSetAttribute(hmma_gemm_kernel<2>,
                         cudaFuncAttributeMaxDynamicSharedMemorySize, GEMM_SMEM);

    dim3 tsB(32, 8);

    // launch 1
    embed_kernel<<<(ROWS * D_MODEL + 255) / 256, 256>>>(tokens, embedding);

    for (int i = 0; i < N_LAYER; i++) {
        const float* w_norm = norm_w   + (size_t)i * D_MODEL;
        const float* w_cw   = conv_w   + (size_t)i * D_INNER * D_CONV;
        const float* w_cb   = conv_b   + (size_t)i * D_INNER;
        const float* w_dtw  = dt_w     + (size_t)i * DT_RANK * D_INNER;
        const float* w_dtb  = dt_b     + (size_t)i * D_INNER;
        const float* w_Alog = A_log    + (size_t)i * D_INNER * D_STATE;
        const float* w_D    = Dp       + (size_t)i * D_INNER;

        // per-layer weight prep (launches 2..4 for layer 0)
        tsplit_kernel<<<dim3(D_MODEL / 32, (2 * D_INNER) / 32), tsB>>>(
            in_proj + (size_t)i * D_MODEL * 2 * D_INNER,
            pwin_h + (size_t)i * 2 * D_INNER * D_MODEL,
            pwin_l + (size_t)i * 2 * D_INNER * D_MODEL, D_MODEL, 2 * D_INNER);
        tsplit_kernel<<<dim3(D_INNER / 32, D_MODEL / 32), tsB>>>(
            out_proj + (size_t)i * D_INNER * D_MODEL,
            pwout_h + (size_t)i * D_MODEL * D_INNER,
            pwout_l + (size_t)i * D_MODEL * D_INNER, D_INNER, D_MODEL);
        tsplit_kernel<<<dim3(D_INNER / 32, XP_N / 32), tsB>>>(
            x_proj + (size_t)i * D_INNER * XP_N,
            pwxp_h + (size_t)i * XP_NPAD * D_INNER,
            pwxp_l + (size_t)i * XP_NPAD * D_INNER, D_INNER, XP_N);

        // launch 5 (layer 0)
        rmsnorm_kernel<<<ROWS, 256>>>(px, w_norm, pah, pal);

        // launch 6 (layer 0)  <-- ncu capture target
        hmma_gemm_kernel<0><<<dim3(ROWS / 128, (2 * D_INNER) / 128), 256, GEMM_SMEM>>>(
            ROWS, 2 * D_INNER, D_MODEL, D_MODEL, D_MODEL, pah, pal,
            pwin_h + (size_t)i * 2 * D_INNER * D_MODEL,
            pwin_l + (size_t)i * 2 * D_INNER * D_MODEL,
            pxz, 2 * D_INNER, nullptr);

        conv_silu_kernel<<<(ROWS * D_INNER + 255) / 256, 256>>>(w_cw, w_cb);

        // dbl = u @ x_proj : HMMA, N=96 (padded weight rows), col-guarded store
        hmma_gemm_kernel<0><<<dim3(ROWS / 128, 1), 256, GEMM_SMEM>>>(
            ROWS, XP_N, D_INNER, D_INNER, D_INNER, pah, pal,
            pwxp_h + (size_t)i * XP_NPAD * D_INNER,
            pwxp_l + (size_t)i * XP_NPAD * D_INNER,
            pdbl, XP_N, nullptr);

        // dt = softplus(dbl[:, :64] @ dt_w + dt_b)
        sgemm_sp_kernel<<<dim3(D_INNER / 128, ROWS / 128), 256>>>(
            ROWS, D_INNER, DT_RANK, pdbl, XP_N, w_dtw, D_INNER,
            pdt, D_INNER, w_dtb);

        scan_kernel<<<256, 256>>>(w_Alog, w_D);

        // x = y @ out_proj + x
        hmma_gemm_kernel<2><<<dim3(ROWS / 128, D_MODEL / 128), 256, GEMM_SMEM>>>(
            ROWS, D_MODEL, D_INNER, D_INNER, D_INNER, pah, pal,
            pwout_h + (size_t)i * D_MODEL * D_INNER,
            pwout_l + (size_t)i * D_MODEL * D_INNER,
            px, D_MODEL, px);
    }

    rmsnorm_kernel<<<ROWS, 256>>>(px, fnorm_w, pah, pal);

    tsplit_kernel<<<dim3(D_MODEL / 32, VOCAB / 32), tsB>>>(
        head_w, phd_h, phd_l, D_MODEL, VOCAB);

    // logits = xn @ head_w
    hmma_gemm_kernel<0><<<dim3(ROWS / 128, VOCAB / 128), 256, GEMM_SMEM>>>(
        ROWS, VOCAB, D_MODEL, D_MODEL, D_MODEL, pah, pal, phd_h, phd_l,
        out, VOCAB, nullptr);
}